// round 3
// baseline (speedup 1.0000x reference)
#include <cuda_runtime.h>
#include <cstdint>
#include <math.h>

#define BB 2
#define NN 512
#define CC 256
#define HH 256
#define WW 256
#define HWP 65536
#define POOLN 7
#define DIN 12544
#define OUTD 1024
#define NROI 1024
#define NCLS 11

// Scratch (device globals; allocation-free per harness rules)
__device__ float g_featT[(size_t)BB * HWP * CC];   // NHWC feat, 134 MB
__device__ float g_x[(size_t)NROI * DIN];          // pooled features, bin-major
__device__ float g_h1[(size_t)NROI * OUTD];
__device__ float g_h2[(size_t)NROI * OUTD];

// ---------------------------------------------------------------------------
// NCHW -> NHWC transpose (per batch: (C, HW) -> (HW, C)), 32x32 smem tiles
// ---------------------------------------------------------------------------
__global__ void transpose_kernel(const float* __restrict__ feat) {
    __shared__ float tile[32][33];
    int b  = blockIdx.z;
    int p0 = blockIdx.x * 32;   // pixel tile
    int c0 = blockIdx.y * 32;   // channel tile
    const float* in = feat + (size_t)b * CC * HWP;
    float* out      = g_featT + (size_t)b * HWP * CC;
    int tx = threadIdx.x, ty = threadIdx.y;
#pragma unroll
    for (int i = 0; i < 32; i += 8)
        tile[ty + i][tx] = in[(size_t)(c0 + ty + i) * HWP + p0 + tx];
    __syncthreads();
#pragma unroll
    for (int i = 0; i < 32; i += 8)
        out[(size_t)(p0 + ty + i) * CC + c0 + tx] = tile[tx][ty + i];
}

// ---------------------------------------------------------------------------
// Rotated ROI align. One block per ROI, one thread per channel.
// Writes g_x[r][bin*256 + c]  (bin = ph*7+pw), i.e. bin-major layout.
// ---------------------------------------------------------------------------
__global__ void roi_kernel(const float* __restrict__ proposals) {
    int r = blockIdx.x;          // 0..1023
    int b = r >> 9;
    int c = threadIdx.x;         // channel
    const float* pr = proposals + r * 5;
    float cx = pr[0], cy = pr[1], w = pr[2], h = pr[3], th = pr[4];
    float cs = cosf(th), sn = sinf(th);
    const float* fb = g_featT + (size_t)b * HWP * CC;
    float* xo = g_x + (size_t)r * DIN;

    float hstep = h / (float)POOLN;
    float wstep = w / (float)POOLN;

    for (int bin = 0; bin < 49; ++bin) {
        int ph = bin / 7, pw = bin % 7;
        float acc = 0.f;
#pragma unroll
        for (int s = 0; s < 4; ++s) {
            int sy = s >> 1, sx = s & 1;
            float yl = -h * 0.5f + hstep * ((float)ph + ((float)sy + 0.5f) * 0.5f);
            float xl = -w * 0.5f + wstep * ((float)pw + ((float)sx + 0.5f) * 0.5f);
            float gx = cx + xl * cs - yl * sn;
            float gy = cy + xl * sn + yl * cs;
            if (gy > -1.f && gy < (float)HH && gx > -1.f && gx < (float)WW) {
                float y = fminf(fmaxf(gy, 0.f), 255.f);
                float x = fminf(fmaxf(gx, 0.f), 255.f);
                float y0f = floorf(y), x0f = floorf(x);
                int y0 = (int)y0f, x0 = (int)x0f;
                int y1 = min(y0 + 1, 255), x1 = min(x0 + 1, 255);
                float ly = y - y0f, lx = x - x0f;
                float hy = 1.f - ly, hx = 1.f - lx;
                float f00 = fb[((size_t)y0 * WW + x0) * CC + c];
                float f01 = fb[((size_t)y0 * WW + x1) * CC + c];
                float f10 = fb[((size_t)y1 * WW + x0) * CC + c];
                float f11 = fb[((size_t)y1 * WW + x1) * CC + c];
                acc += hy * hx * f00 + hy * lx * f01 + ly * hx * f10 + ly * lx * f11;
            }
        }
        xo[bin * CC + c] = acc * 0.25f;
    }
}

// ---------------------------------------------------------------------------
// TF32 tensor-core GEMM + bias + relu, double-buffered.
// C[M=1024, N=1024] = relu(A[M,K] @ Bw[K,N] + bias)
// STAGE 1: A=g_x, W1 row-permuted k -> (k%256)*49 + k/256, K=12544.
// STAGE 2: A=g_h1, W2 identity, K=1024.
// BM=64, BN=64, BK=32, 128 threads (4 warps, 2x2), warp tile 32x32.
// As: [m][k] stride 36 (conflict-free STS.128 + fragment LDS)
// Bs: [k][n] stride 72 (conflict-free)
// ---------------------------------------------------------------------------
__device__ __forceinline__ uint32_t f2tf(float f) {
    uint32_t u;
    asm("cvt.rna.tf32.f32 %0, %1;" : "=r"(u) : "f"(f));
    return u;
}

__device__ __forceinline__ void mma_tf32(float c[4], const uint32_t a[4], const uint32_t b[2]) {
    asm volatile(
        "mma.sync.aligned.m16n8k8.row.col.f32.tf32.tf32.f32 "
        "{%0,%1,%2,%3},{%4,%5,%6,%7},{%8,%9},{%0,%1,%2,%3};"
        : "+f"(c[0]), "+f"(c[1]), "+f"(c[2]), "+f"(c[3])
        : "r"(a[0]), "r"(a[1]), "r"(a[2]), "r"(a[3]), "r"(b[0]), "r"(b[1]));
}

#define SA 36    // 36 % 32 == 4 -> A frag banks (4g+tig) all distinct
#define SB 72    // 72 % 32 == 8 -> B frag banks (8tig+g) all distinct

template <int STAGE>
__global__ void __launch_bounds__(128)
gemm_tc(const float* __restrict__ Bw, const float* __restrict__ bias, int K) {
    const int N = 1024;
    const float* A = (STAGE == 1) ? g_x : g_h1;
    float* C       = (STAGE == 1) ? g_h1 : g_h2;
    constexpr bool PERM = (STAGE == 1);

    __shared__ uint32_t As[2][64][SA];   // [buf][m][k]
    __shared__ uint32_t Bs[2][32][SB];   // [buf][k][n]

    int tid = threadIdx.x;
    int bm = blockIdx.y * 64, bn = blockIdx.x * 64;

    // producer mapping
    int amr = tid >> 1;              // A row 0..63
    int akq = (tid & 1) * 16;        // A k half
    int bkr = tid >> 2;              // B k row 0..31
    int bn0 = (tid & 3) * 16;        // B n start

    // consumer mapping
    int warpId = tid >> 5;
    int lane = tid & 31;
    int wm = warpId >> 1;            // 0..1
    int wn = warpId & 1;             // 0..1
    int g = lane >> 2, tig = lane & 3;

    float acc[2][4][4];
#pragma unroll
    for (int mt = 0; mt < 2; mt++)
#pragma unroll
        for (int nt = 0; nt < 4; nt++)
#pragma unroll
            for (int i = 0; i < 4; i++) acc[mt][nt][i] = 0.f;

    const int numTiles = K / 32;
    float4 pa[4], pb[4];

    // prefetch tile 0 into registers
    {
        const float* arow = A + (size_t)(bm + amr) * K + akq;
#pragma unroll
        for (int j = 0; j < 4; j++) pa[j] = *(const float4*)(arow + 4 * j);
        int gk = bkr;
        int prow = PERM ? ((gk & 255) * 49 + (gk >> 8)) : gk;
        const float* brow = Bw + (size_t)prow * N + bn + bn0;
#pragma unroll
        for (int j = 0; j < 4; j++) pb[j] = *(const float4*)(brow + 4 * j);
    }
    // store tile 0 into buffer 0
#pragma unroll
    for (int j = 0; j < 4; j++)
        *(uint4*)&As[0][amr][akq + 4 * j] =
            make_uint4(f2tf(pa[j].x), f2tf(pa[j].y), f2tf(pa[j].z), f2tf(pa[j].w));
#pragma unroll
    for (int j = 0; j < 4; j++)
        *(uint4*)&Bs[0][bkr][bn0 + 4 * j] =
            make_uint4(f2tf(pb[j].x), f2tf(pb[j].y), f2tf(pb[j].z), f2tf(pb[j].w));
    __syncthreads();

    for (int t = 0; t < numTiles; ++t) {
        int buf = t & 1;
        // issue global prefetch for tile t+1
        if (t + 1 < numTiles) {
            int k0 = (t + 1) * 32;
            const float* arow = A + (size_t)(bm + amr) * K + k0 + akq;
#pragma unroll
            for (int j = 0; j < 4; j++) pa[j] = *(const float4*)(arow + 4 * j);
            int gk = k0 + bkr;
            int prow = PERM ? ((gk & 255) * 49 + (gk >> 8)) : gk;
            const float* brow = Bw + (size_t)prow * N + bn + bn0;
#pragma unroll
            for (int j = 0; j < 4; j++) pb[j] = *(const float4*)(brow + 4 * j);
        }

        // compute on current buffer: 4 k-steps of m16n8k8
#pragma unroll
        for (int ks = 0; ks < 4; ks++) {
            int kb = ks * 8;
            uint32_t afr[2][4], bfr[4][2];
#pragma unroll
            for (int mt = 0; mt < 2; mt++) {
                int m0 = wm * 32 + mt * 16;
                afr[mt][0] = As[buf][m0 + g][kb + tig];
                afr[mt][1] = As[buf][m0 + 8 + g][kb + tig];
                afr[mt][2] = As[buf][m0 + g][kb + tig + 4];
                afr[mt][3] = As[buf][m0 + 8 + g][kb + tig + 4];
            }
#pragma unroll
            for (int nt = 0; nt < 4; nt++) {
                int n0 = wn * 32 + nt * 8;
                bfr[nt][0] = Bs[buf][kb + tig][n0 + g];
                bfr[nt][1] = Bs[buf][kb + tig + 4][n0 + g];
            }
#pragma unroll
            for (int mt = 0; mt < 2; mt++)
#pragma unroll
                for (int nt = 0; nt < 4; nt++)
                    mma_tf32(acc[mt][nt], afr[mt], bfr[nt]);
        }

        // store prefetched tile into the other buffer
        if (t + 1 < numTiles) {
            int nb = buf ^ 1;
#pragma unroll
            for (int j = 0; j < 4; j++)
                *(uint4*)&As[nb][amr][akq + 4 * j] =
                    make_uint4(f2tf(pa[j].x), f2tf(pa[j].y), f2tf(pa[j].z), f2tf(pa[j].w));
#pragma unroll
            for (int j = 0; j < 4; j++)
                *(uint4*)&Bs[nb][bkr][bn0 + 4 * j] =
                    make_uint4(f2tf(pb[j].x), f2tf(pb[j].y), f2tf(pb[j].z), f2tf(pb[j].w));
        }
        __syncthreads();
    }

    // epilogue: bias + relu, float2 stores
#pragma unroll
    for (int mt = 0; mt < 2; mt++) {
        int r0 = bm + wm * 32 + mt * 16 + g;
        int r1 = r0 + 8;
#pragma unroll
        for (int nt = 0; nt < 4; nt++) {
            int cb = bn + wn * 32 + nt * 8 + tig * 2;
            float2 bv = *(const float2*)&bias[cb];
            float2 o0, o1;
            o0.x = fmaxf(acc[mt][nt][0] + bv.x, 0.f);
            o0.y = fmaxf(acc[mt][nt][1] + bv.y, 0.f);
            o1.x = fmaxf(acc[mt][nt][2] + bv.x, 0.f);
            o1.y = fmaxf(acc[mt][nt][3] + bv.y, 0.f);
            *(float2*)&C[(size_t)r0 * N + cb] = o0;
            *(float2*)&C[(size_t)r1 * N + cb] = o1;
        }
    }
}

// ---------------------------------------------------------------------------
// Head: cls (11) + reg (5) GEMV per ROI + box decode.
// Output layout: boxes [0, 5120), cls [5120, 16384)
// ---------------------------------------------------------------------------
__global__ void head_kernel(const float* __restrict__ proposals,
                            const float* __restrict__ Wcls, const float* __restrict__ bcls,
                            const float* __restrict__ Wreg, const float* __restrict__ breg,
                            float* __restrict__ out) {
    int r = blockIdx.x;
    int tid = threadIdx.x;
    int j = tid >> 4, lane = tid & 15;   // 16 outputs x 16 lanes
    __shared__ float sred[16];
    const float* hrow = g_h2 + (size_t)r * OUTD;

    float s = 0.f;
    if (j < 11) {
        for (int k = lane; k < OUTD; k += 16) s += hrow[k] * Wcls[k * 11 + j];
    } else {
        int jj = j - 11;
        for (int k = lane; k < OUTD; k += 16) s += hrow[k] * Wreg[k * 5 + jj];
    }
#pragma unroll
    for (int off = 8; off; off >>= 1) s += __shfl_down_sync(0xffffffffu, s, off, 16);
    if (lane == 0) {
        float bb = (j < 11) ? bcls[j] : breg[j - 11];
        sred[j] = s + bb;
    }
    __syncthreads();

    if (tid < 11) out[NROI * 5 + r * 11 + tid] = sred[tid];
    if (tid == 0) {
        const float* pr = proposals + r * 5;
        float p0 = pr[0] * 4.f, p1 = pr[1] * 4.f;
        float p2 = pr[2] * 4.f, p3 = pr[3] * 4.f, p4 = pr[4];
        float r0 = sred[11], r1 = sred[12], r2 = sred[13], r3 = sred[14], r4 = sred[15];
        const float CLV = 4.1351665567423560f;     // |log(16/1000)|
        const float PI  = 3.14159265358979323846f;
        float bx = p2 * r0 + p0;
        float by = p3 * r1 + p1;
        float bw = p2 * expf(fminf(fmaxf(r2, -CLV), CLV));
        float bh = p3 * expf(fminf(fmaxf(r3, -CLV), CLV));
        float a2 = p4 + r4 + PI * 0.5f;
        float m  = a2 - floorf(a2 / PI) * PI;      // python-mod semantics, [0, pi)
        float ba = m - PI * 0.5f;
        float* ob = out + r * 5;
        ob[0] = bx; ob[1] = by; ob[2] = bw; ob[3] = bh; ob[4] = ba;
    }
}

extern "C" void kernel_launch(void* const* d_in, const int* in_sizes, int n_in,
                              void* d_out, int out_size) {
    const float* feat      = (const float*)d_in[0];
    const float* proposals = (const float*)d_in[1];
    const float* W1   = (const float*)d_in[2];
    const float* b1   = (const float*)d_in[3];
    const float* W2   = (const float*)d_in[4];
    const float* b2   = (const float*)d_in[5];
    const float* Wcls = (const float*)d_in[6];
    const float* bcls = (const float*)d_in[7];
    const float* Wreg = (const float*)d_in[8];
    const float* breg = (const float*)d_in[9];
    float* out = (float*)d_out;

    transpose_kernel<<<dim3(HWP / 32, CC / 32, BB), dim3(32, 8)>>>(feat);
    roi_kernel<<<NROI, 256>>>(proposals);
    gemm_tc<1><<<dim3(16, 16), 128>>>(W1, b1, DIN);   // x @ W1 -> h1
    gemm_tc<2><<<dim3(16, 16), 128>>>(W2, b2, OUTD);  // h1 @ W2 -> h2
    head_kernel<<<NROI, 256>>>(proposals, Wcls, bcls, Wreg, breg, out);
}

// round 4
// speedup vs baseline: 1.1692x; 1.1692x over previous
#include <cuda_runtime.h>
#include <cstdint>
#include <math.h>

#define BB 2
#define NN 512
#define CC 256
#define HH 256
#define WW 256
#define HWP 65536
#define POOLN 7
#define DIN 12544
#define OUTD 1024
#define NROI 1024
#define NCLS 11
#define KSPLIT 4

// Scratch (device globals; allocation-free per harness rules)
__device__ float g_featT[(size_t)BB * HWP * CC];   // NHWC feat, 134 MB
__device__ float g_x[(size_t)NROI * DIN];          // pooled features, bin-major
__device__ float g_part[(size_t)KSPLIT * NROI * OUTD];  // GEMM1 split-K partials
__device__ float g_h1[(size_t)NROI * OUTD];
__device__ float g_h2[(size_t)NROI * OUTD];

// ---------------------------------------------------------------------------
// NCHW -> NHWC transpose (per batch: (C, HW) -> (HW, C)), 32x32 smem tiles
// ---------------------------------------------------------------------------
__global__ void transpose_kernel(const float* __restrict__ feat) {
    __shared__ float tile[32][33];
    int b  = blockIdx.z;
    int p0 = blockIdx.x * 32;
    int c0 = blockIdx.y * 32;
    const float* in = feat + (size_t)b * CC * HWP;
    float* out      = g_featT + (size_t)b * HWP * CC;
    int tx = threadIdx.x, ty = threadIdx.y;
#pragma unroll
    for (int i = 0; i < 32; i += 8)
        tile[ty + i][tx] = in[(size_t)(c0 + ty + i) * HWP + p0 + tx];
    __syncthreads();
#pragma unroll
    for (int i = 0; i < 32; i += 8)
        out[(size_t)(p0 + ty + i) * CC + c0 + tx] = tile[tx][ty + i];
}

// ---------------------------------------------------------------------------
// Rotated ROI align. One block per ROI, one thread per channel.
// ---------------------------------------------------------------------------
__global__ void roi_kernel(const float* __restrict__ proposals) {
    int r = blockIdx.x;
    int b = r >> 9;
    int c = threadIdx.x;
    const float* pr = proposals + r * 5;
    float cx = pr[0], cy = pr[1], w = pr[2], h = pr[3], th = pr[4];
    float cs = cosf(th), sn = sinf(th);
    const float* fb = g_featT + (size_t)b * HWP * CC;
    float* xo = g_x + (size_t)r * DIN;

    float hstep = h / (float)POOLN;
    float wstep = w / (float)POOLN;

    for (int bin = 0; bin < 49; ++bin) {
        int ph = bin / 7, pw = bin % 7;
        float acc = 0.f;
#pragma unroll
        for (int s = 0; s < 4; ++s) {
            int sy = s >> 1, sx = s & 1;
            float yl = -h * 0.5f + hstep * ((float)ph + ((float)sy + 0.5f) * 0.5f);
            float xl = -w * 0.5f + wstep * ((float)pw + ((float)sx + 0.5f) * 0.5f);
            float gx = cx + xl * cs - yl * sn;
            float gy = cy + xl * sn + yl * cs;
            if (gy > -1.f && gy < (float)HH && gx > -1.f && gx < (float)WW) {
                float y = fminf(fmaxf(gy, 0.f), 255.f);
                float x = fminf(fmaxf(gx, 0.f), 255.f);
                float y0f = floorf(y), x0f = floorf(x);
                int y0 = (int)y0f, x0 = (int)x0f;
                int y1 = min(y0 + 1, 255), x1 = min(x0 + 1, 255);
                float ly = y - y0f, lx = x - x0f;
                float hy = 1.f - ly, hx = 1.f - lx;
                float f00 = fb[((size_t)y0 * WW + x0) * CC + c];
                float f01 = fb[((size_t)y0 * WW + x1) * CC + c];
                float f10 = fb[((size_t)y1 * WW + x0) * CC + c];
                float f11 = fb[((size_t)y1 * WW + x1) * CC + c];
                acc += hy * hx * f00 + hy * lx * f01 + ly * hx * f10 + ly * lx * f11;
            }
        }
        xo[bin * CC + c] = acc * 0.25f;
    }
}

// ---------------------------------------------------------------------------
// TF32 tensor-core GEMM, double-buffered smem + frag pipelining.
// STAGE 1: A=g_x, W1 k-permuted rows, split-K over blockIdx.z -> g_part (raw)
// STAGE 2: A=g_h1, W2, bias+relu epilogue -> g_h2
// BM=64, BN=64, BK=32, 128 threads (4 warps 2x2), warp tile 32x32.
// Smem layout: As[m][40], Bs[n][40], k-permuted p(k)=(k%4)*2+k/4 per 8-group
// so each fragment load is a single LDS.64 (k=tig, k=tig+4), bank-clean.
// ---------------------------------------------------------------------------
__device__ __forceinline__ uint32_t f2tf(float f) {
    uint32_t u;
    asm("cvt.rna.tf32.f32 %0, %1;" : "=r"(u) : "f"(f));
    return u;
}

__device__ __forceinline__ void mma_tf32(float c[4], const uint32_t a[4], const uint32_t b[2]) {
    asm volatile(
        "mma.sync.aligned.m16n8k8.row.col.f32.tf32.tf32.f32 "
        "{%0,%1,%2,%3},{%4,%5,%6,%7},{%8,%9},{%0,%1,%2,%3};"
        : "+f"(c[0]), "+f"(c[1]), "+f"(c[2]), "+f"(c[3])
        : "r"(a[0]), "r"(a[1]), "r"(a[2]), "r"(a[3]), "r"(b[0]), "r"(b[1]));
}

#define SROW 40   // 32 k-words + 8 pad; (8*row + 2*tig) mod 32 distinct per half-warp

template <int STAGE>
__global__ void __launch_bounds__(128)
gemm_tc(const float* __restrict__ Bw, const float* __restrict__ bias,
        int klen, int kstride) {
    const int N = 1024;
    const float* A = (STAGE == 1) ? g_x : g_h1;
    float* C = (STAGE == 1) ? (g_part + (size_t)blockIdx.z * NROI * OUTD) : g_h2;
    constexpr bool PERM = (STAGE == 1);

    __shared__ uint32_t As[2][64][SROW];
    __shared__ uint32_t Bs[2][64][SROW];

    int tid = threadIdx.x;
    int bm = blockIdx.y * 64, bn = blockIdx.x * 64;
    int kbase = blockIdx.z * klen;

    // producer A: row amr, k-half akq (16 wide)
    int amr = tid >> 1;
    int akq = (tid & 1) * 16;
    // producer B: n-row bnr, k-half bkh (16 wide)
    int bnr = tid >> 1;
    int bkh = (tid & 1) * 16;

    // consumer
    int warpId = tid >> 5;
    int lane = tid & 31;
    int wm = warpId >> 1;
    int wn = warpId & 1;
    int g = lane >> 2, tig = lane & 3;

    float acc[2][4][4];
#pragma unroll
    for (int mt = 0; mt < 2; mt++)
#pragma unroll
        for (int nt = 0; nt < 4; nt++)
#pragma unroll
            for (int i = 0; i < 4; i++) acc[mt][nt][i] = 0.f;

    const int numTiles = klen / 32;
    float4 pa[4];
    float pb[16];

    // ---- global fetch helpers (register prefetch) ----
#define FETCH_A(k0)                                                         \
    {                                                                       \
        const float* arow = A + (size_t)(bm + amr) * kstride + (k0) + akq;  \
        pa[0] = *(const float4*)(arow);                                     \
        pa[1] = *(const float4*)(arow + 4);                                 \
        pa[2] = *(const float4*)(arow + 8);                                 \
        pa[3] = *(const float4*)(arow + 12);                                \
    }
#define FETCH_B(k0)                                                         \
    {                                                                       \
        _Pragma("unroll")                                                   \
        for (int j = 0; j < 16; j++) {                                      \
            int gk = (k0) + bkh + j;                                        \
            int prow = PERM ? ((gk & 255) * 49 + (gk >> 8)) : gk;           \
            pb[j] = __ldg(&Bw[(size_t)prow * N + bn + bnr]);                \
        }                                                                   \
    }
    // permuted store of a 8-group (v0..v7) at word base wb of row ptr
#define STORE_GRP(rowptr, wb, v0, v1, v2, v3, v4, v5, v6, v7)               \
    {                                                                       \
        *(uint4*)&(rowptr)[(wb)] =                                          \
            make_uint4(f2tf(v0), f2tf(v4), f2tf(v1), f2tf(v5));             \
        *(uint4*)&(rowptr)[(wb) + 4] =                                      \
            make_uint4(f2tf(v2), f2tf(v6), f2tf(v3), f2tf(v7));             \
    }
#define STORE_TILE(buf)                                                     \
    {                                                                       \
        uint32_t* ar = As[buf][amr];                                        \
        STORE_GRP(ar, akq, pa[0].x, pa[0].y, pa[0].z, pa[0].w,              \
                  pa[1].x, pa[1].y, pa[1].z, pa[1].w);                      \
        STORE_GRP(ar, akq + 8, pa[2].x, pa[2].y, pa[2].z, pa[2].w,          \
                  pa[3].x, pa[3].y, pa[3].z, pa[3].w);                      \
        uint32_t* br = Bs[buf][bnr];                                        \
        STORE_GRP(br, bkh, pb[0], pb[1], pb[2], pb[3],                      \
                  pb[4], pb[5], pb[6], pb[7]);                              \
        STORE_GRP(br, bkh + 8, pb[8], pb[9], pb[10], pb[11],                \
                  pb[12], pb[13], pb[14], pb[15]);                          \
    }

    FETCH_A(kbase);
    FETCH_B(kbase);
    STORE_TILE(0);
    __syncthreads();

    for (int t = 0; t < numTiles; ++t) {
        int buf = t & 1;
        if (t + 1 < numTiles) {
            int k0 = kbase + (t + 1) * 32;
            FETCH_A(k0);
            FETCH_B(k0);
        }

        // fragment-pipelined compute over 4 k-steps
        uint2 fa[2][2], fb[4];
        {
            int m0 = wm * 32;
#pragma unroll
            for (int mt = 0; mt < 2; mt++) {
                fa[mt][0] = *(const uint2*)&As[buf][m0 + mt * 16 + g][2 * tig];
                fa[mt][1] = *(const uint2*)&As[buf][m0 + mt * 16 + 8 + g][2 * tig];
            }
#pragma unroll
            for (int nt = 0; nt < 4; nt++)
                fb[nt] = *(const uint2*)&Bs[buf][wn * 32 + nt * 8 + g][2 * tig];
        }
#pragma unroll
        for (int ks = 0; ks < 4; ks++) {
            uint2 na[2][2], nb[4];
            if (ks < 3) {
                int kb = (ks + 1) * 8;
                int m0 = wm * 32;
#pragma unroll
                for (int mt = 0; mt < 2; mt++) {
                    na[mt][0] = *(const uint2*)&As[buf][m0 + mt * 16 + g][kb + 2 * tig];
                    na[mt][1] = *(const uint2*)&As[buf][m0 + mt * 16 + 8 + g][kb + 2 * tig];
                }
#pragma unroll
                for (int nt = 0; nt < 4; nt++)
                    nb[nt] = *(const uint2*)&Bs[buf][wn * 32 + nt * 8 + g][kb + 2 * tig];
            }
#pragma unroll
            for (int mt = 0; mt < 2; mt++) {
                uint32_t afr[4] = {fa[mt][0].x, fa[mt][1].x, fa[mt][0].y, fa[mt][1].y};
#pragma unroll
                for (int nt = 0; nt < 4; nt++) {
                    uint32_t bfr[2] = {fb[nt].x, fb[nt].y};
                    mma_tf32(acc[mt][nt], afr, bfr);
                }
            }
            if (ks < 3) {
#pragma unroll
                for (int mt = 0; mt < 2; mt++) {
                    fa[mt][0] = na[mt][0];
                    fa[mt][1] = na[mt][1];
                }
#pragma unroll
                for (int nt = 0; nt < 4; nt++) fb[nt] = nb[nt];
            }
        }

        if (t + 1 < numTiles) {
            STORE_TILE(buf ^ 1);
        }
        __syncthreads();
    }

    // epilogue
#pragma unroll
    for (int mt = 0; mt < 2; mt++) {
        int r0 = bm + wm * 32 + mt * 16 + g;
        int r1 = r0 + 8;
#pragma unroll
        for (int nt = 0; nt < 4; nt++) {
            int cb = bn + wn * 32 + nt * 8 + tig * 2;
            float2 o0, o1;
            if (STAGE == 1) {   // raw partials, combined later
                o0.x = acc[mt][nt][0]; o0.y = acc[mt][nt][1];
                o1.x = acc[mt][nt][2]; o1.y = acc[mt][nt][3];
            } else {
                float2 bv = *(const float2*)&bias[cb];
                o0.x = fmaxf(acc[mt][nt][0] + bv.x, 0.f);
                o0.y = fmaxf(acc[mt][nt][1] + bv.y, 0.f);
                o1.x = fmaxf(acc[mt][nt][2] + bv.x, 0.f);
                o1.y = fmaxf(acc[mt][nt][3] + bv.y, 0.f);
            }
            *(float2*)&C[(size_t)r0 * N + cb] = o0;
            *(float2*)&C[(size_t)r1 * N + cb] = o1;
        }
    }
#undef FETCH_A
#undef FETCH_B
#undef STORE_GRP
#undef STORE_TILE
}

// ---------------------------------------------------------------------------
// Combine split-K partials + bias + relu -> g_h1 (fixed order, deterministic)
// ---------------------------------------------------------------------------
__global__ void combine_kernel(const float* __restrict__ bias) {
    int idx = (blockIdx.x * 256 + threadIdx.x) * 4;   // element offset
    const size_t P = (size_t)NROI * OUTD;
    float4 s = *(const float4*)&g_part[idx];
#pragma unroll
    for (int z = 1; z < KSPLIT; z++) {
        float4 p = *(const float4*)&g_part[z * P + idx];
        s.x += p.x; s.y += p.y; s.z += p.z; s.w += p.w;
    }
    float4 bv = *(const float4*)&bias[idx & (OUTD - 1)];
    s.x = fmaxf(s.x + bv.x, 0.f);
    s.y = fmaxf(s.y + bv.y, 0.f);
    s.z = fmaxf(s.z + bv.z, 0.f);
    s.w = fmaxf(s.w + bv.w, 0.f);
    *(float4*)&g_h1[idx] = s;
}

// ---------------------------------------------------------------------------
// Head: cls (11) + reg (5) GEMV per ROI + box decode.
// ---------------------------------------------------------------------------
__global__ void head_kernel(const float* __restrict__ proposals,
                            const float* __restrict__ Wcls, const float* __restrict__ bcls,
                            const float* __restrict__ Wreg, const float* __restrict__ breg,
                            float* __restrict__ out) {
    int r = blockIdx.x;
    int tid = threadIdx.x;
    int j = tid >> 4, lane = tid & 15;
    __shared__ float sred[16];
    const float* hrow = g_h2 + (size_t)r * OUTD;

    float s = 0.f;
    if (j < 11) {
        for (int k = lane; k < OUTD; k += 16) s += hrow[k] * Wcls[k * 11 + j];
    } else {
        int jj = j - 11;
        for (int k = lane; k < OUTD; k += 16) s += hrow[k] * Wreg[k * 5 + jj];
    }
#pragma unroll
    for (int off = 8; off; off >>= 1) s += __shfl_down_sync(0xffffffffu, s, off, 16);
    if (lane == 0) {
        float bb = (j < 11) ? bcls[j] : breg[j - 11];
        sred[j] = s + bb;
    }
    __syncthreads();

    if (tid < 11) out[NROI * 5 + r * 11 + tid] = sred[tid];
    if (tid == 0) {
        const float* pr = proposals + r * 5;
        float p0 = pr[0] * 4.f, p1 = pr[1] * 4.f;
        float p2 = pr[2] * 4.f, p3 = pr[3] * 4.f, p4 = pr[4];
        float r0 = sred[11], r1 = sred[12], r2 = sred[13], r3 = sred[14], r4 = sred[15];
        const float CLV = 4.1351665567423560f;
        const float PI  = 3.14159265358979323846f;
        float bx = p2 * r0 + p0;
        float by = p3 * r1 + p1;
        float bw = p2 * expf(fminf(fmaxf(r2, -CLV), CLV));
        float bh = p3 * expf(fminf(fmaxf(r3, -CLV), CLV));
        float a2 = p4 + r4 + PI * 0.5f;
        float m  = a2 - floorf(a2 / PI) * PI;
        float ba = m - PI * 0.5f;
        float* ob = out + r * 5;
        ob[0] = bx; ob[1] = by; ob[2] = bw; ob[3] = bh; ob[4] = ba;
    }
}

extern "C" void kernel_launch(void* const* d_in, const int* in_sizes, int n_in,
                              void* d_out, int out_size) {
    const float* feat      = (const float*)d_in[0];
    const float* proposals = (const float*)d_in[1];
    const float* W1   = (const float*)d_in[2];
    const float* b1   = (const float*)d_in[3];
    const float* W2   = (const float*)d_in[4];
    const float* b2   = (const float*)d_in[5];
    const float* Wcls = (const float*)d_in[6];
    const float* bcls = (const float*)d_in[7];
    const float* Wreg = (const float*)d_in[8];
    const float* breg = (const float*)d_in[9];
    float* out = (float*)d_out;

    transpose_kernel<<<dim3(HWP / 32, CC / 32, BB), dim3(32, 8)>>>(feat);
    roi_kernel<<<NROI, 256>>>(proposals);
    gemm_tc<1><<<dim3(16, 16, KSPLIT), 128>>>(W1, b1, DIN / KSPLIT, DIN);
    combine_kernel<<<(NROI * OUTD / 4) / 256, 256>>>(b1);
    gemm_tc<2><<<dim3(16, 16, 1), 128>>>(W2, b2, OUTD, OUTD);
    head_kernel<<<NROI, 256>>>(proposals, Wcls, bcls, Wreg, breg, out);
}